// round 1
// baseline (speedup 1.0000x reference)
#include <cuda_runtime.h>
#include <cstdint>

// Problem constants (fixed by the reference)
// x: (8, 16, 4096, 128) fp32, R: (128, 128, 4096) fp32
// out[b,h,s,d] = R[d,d,s] * x[b,h,s,d]
#define SEQ   4096
#define DK    128
#define INNER (SEQ * DK)          // 524288 = 2^19 elements per (b,h) slice
#define INNER4 (INNER / 4)        // 131072 float4s per slice
#define NTOT  (8 * 16 * INNER)    // 67108864 elements
#define NTOT4 (NTOT / 4)          // 16777216 float4s

// 2 MB scratch for the transposed diagonal: g_diag[s*128 + d] = R[d,d,s]
__device__ __align__(16) float g_diag[INNER];

// Kernel 1: gather diagonal of R into [s][d] layout.
// t = s*128 + d (coalesced writes). Reads R[(d*129)*4096 + s]: lanes within a
// warp hit 32 distinct lines, but total unique-line footprint is only 2 MB and
// each 128B line is reused by 32 consecutive s -> L2 absorbs it. Cost ~= few us.
__global__ void diag_gather_kernel(const float* __restrict__ R) {
    int t = blockIdx.x * blockDim.x + threadIdx.x;   // 0 .. INNER-1
    if (t >= INNER) return;
    int d = t & (DK - 1);
    int s = t >> 7;
    // R index: (d*DK + d)*SEQ + s = d*129*4096 + s
    g_diag[t] = R[((size_t)d * (DK + 1)) * SEQ + (size_t)s];
}

// Kernel 2: streaming float4 multiply. diag index repeats every INNER elements,
// and INNER4 is a power of two -> mask instead of modulo.
__global__ void __launch_bounds__(256) rope_diag_scale_kernel(
    const float4* __restrict__ x4, float4* __restrict__ out4) {
    size_t i = (size_t)blockIdx.x * blockDim.x + threadIdx.x;   // < NTOT4
    const float4* __restrict__ d4 = reinterpret_cast<const float4*>(g_diag);

    float4 xv = x4[i];
    float4 dv = d4[i & (INNER4 - 1)];
    float4 ov;
    ov.x = xv.x * dv.x;
    ov.y = xv.y * dv.y;
    ov.z = xv.z * dv.z;
    ov.w = xv.w * dv.w;
    out4[i] = ov;
}

extern "C" void kernel_launch(void* const* d_in, const int* in_sizes, int n_in,
                              void* d_out, int out_size) {
    const float* x = (const float*)d_in[0];
    // d_in[1] = token_positions (int64) -- unused, as in the reference
    const float* R = (const float*)d_in[2];
    float* out = (float*)d_out;

    // Kernel 1: 524288 threads
    diag_gather_kernel<<<INNER / 256, 256>>>(R);

    // Kernel 2: 16777216 float4 threads
    rope_diag_scale_kernel<<<NTOT4 / 256, 256>>>(
        (const float4*)x, (float4*)out);
}

// round 4
// speedup vs baseline: 1.0078x; 1.0078x over previous
#include <cuda_runtime.h>
#include <cstdint>

// Problem constants (fixed by the reference)
// x: (8, 16, 4096, 128) fp32, R: (128, 128, 4096) fp32
// out[b,h,s,d] = R[d,d,s] * x[b,h,s,d]
#define SEQ    4096
#define DK     128
#define INNER  (SEQ * DK)          // 524288 elements per (b,h) slice
#define INNER4 (INNER / 4)         // 131072 float4s per slice (power of two)
#define NTOT   (8 * 16 * INNER)    // 67108864 elements
#define NTOT4  (NTOT / 4)          // 16777216 float4s
#define UNROLL 4
#define TPB    256

// 2 MB scratch for the transposed diagonal: g_diag[s*128 + d] = R[d,d,s]
__device__ __align__(16) float g_diag[INNER];

// Kernel 1: gather diagonal of R into [s][d] layout (coalesced writes).
__global__ void diag_gather_kernel(const float* __restrict__ R) {
    int t = blockIdx.x * blockDim.x + threadIdx.x;   // 0 .. INNER-1
    int d = t & (DK - 1);
    int s = t >> 7;
    // R index: (d*DK + d)*SEQ + s
    g_diag[t] = R[((size_t)d * (DK + 1)) * SEQ + (size_t)s];
}

// Kernel 2: streaming float4 multiply, unroll x4 for MLP, evict-first on the
// 268MB x/out streams so the 2MB diag stays L2-resident.
__global__ void __launch_bounds__(TPB) rope_diag_scale_kernel(
    const float4* __restrict__ x4, float4* __restrict__ out4) {
    size_t base = (size_t)blockIdx.x * (TPB * UNROLL) + threadIdx.x;
    const float4* __restrict__ d4 = reinterpret_cast<const float4*>(g_diag);

    float4 xv[UNROLL];
    float4 dv[UNROLL];

    // Batch all loads up front (front-batched MLP = 8 per thread)
    #pragma unroll
    for (int u = 0; u < UNROLL; u++) {
        size_t i = base + (size_t)u * TPB;
        xv[u] = __ldcs(&x4[i]);                       // evict-first stream
    }
    #pragma unroll
    for (int u = 0; u < UNROLL; u++) {
        size_t i = base + (size_t)u * TPB;
        dv[u] = __ldg(&d4[i & (INNER4 - 1)]);         // L2-resident reuse
    }

    #pragma unroll
    for (int u = 0; u < UNROLL; u++) {
        size_t i = base + (size_t)u * TPB;
        float4 ov;
        ov.x = xv[u].x * dv[u].x;
        ov.y = xv[u].y * dv[u].y;
        ov.z = xv[u].z * dv[u].z;
        ov.w = xv[u].w * dv[u].w;
        __stcs(&out4[i], ov);                         // streaming store
    }
}

extern "C" void kernel_launch(void* const* d_in, const int* in_sizes, int n_in,
                              void* d_out, int out_size) {
    const float* x = (const float*)d_in[0];
    // d_in[1] = token_positions (int64) -- unused, as in the reference
    const float* R = (const float*)d_in[2];
    float* out = (float*)d_out;

    diag_gather_kernel<<<INNER / TPB, TPB>>>(R);

    rope_diag_scale_kernel<<<NTOT4 / (TPB * UNROLL), TPB>>>(
        (const float4*)x, (float4*)out);
}

// round 5
// speedup vs baseline: 1.0281x; 1.0201x over previous
#include <cuda_runtime.h>
#include <cstdint>

// x: (8, 16, 4096, 128) fp32, R: (128, 128, 4096) fp32
// out[b,h,s,d] = R[d,d,s] * x[b,h,s,d]
#define SEQ    4096
#define DK     128
#define INNER  (SEQ * DK)          // 524288 elements per (b,h) slice
#define INNER4 (INNER / 4)         // 131072 float4s per slice (power of two)
#define NTOT   (8 * 16 * INNER)    // 67108864 elements
#define NTOT4  (NTOT / 4)          // 16777216 float4s
#define UNROLL 8
#define TPB    256

// Transpose tile dims for the diag gather
#define TD     32                  // d per block
#define TS     128                 // s per block

// 2 MB scratch: g_diag[s*128 + d] = R[d,d,s]
__device__ __align__(16) float g_diag[INNER];

// Kernel 1: gather diagonal of R, transposing [d][s] -> [s][d] via smem so
// both the R loads (along s, float4) and the g_diag stores (along d) coalesce.
// Grid: (DK/TD) * (SEQ/TS) = 4 * 32 = 128 blocks of 256 threads (one wave).
__global__ void __launch_bounds__(TPB) diag_gather_kernel(const float* __restrict__ R) {
    __shared__ float tile[TD][TS + 1];   // +1 pad: conflict-free transposed reads

    int d0 = (blockIdx.x & 3) * TD;      // 0,32,64,96
    int s0 = (blockIdx.x >> 2) * TS;     // 0..3968

    // Load phase: 32 d-rows x 32 float4s (=128 s) = 1024 float4s, 4/thread.
    // Lanes vary along s -> coalesced 512B per warp per load.
    #pragma unroll
    for (int k = 0; k < 4; k++) {
        int idx   = threadIdx.x + k * TPB;     // 0..1023
        int s4    = idx & 31;                  // float4 index along s
        int d_loc = idx >> 5;                  // 0..31
        const float4* src = reinterpret_cast<const float4*>(
            R + (size_t)(d0 + d_loc) * (DK + 1) * SEQ + s0) + s4;
        float4 v = __ldg(src);
        tile[d_loc][s4 * 4 + 0] = v.x;
        tile[d_loc][s4 * 4 + 1] = v.y;
        tile[d_loc][s4 * 4 + 2] = v.z;
        tile[d_loc][s4 * 4 + 3] = v.w;
    }
    __syncthreads();

    // Store phase: lanes vary along d -> contiguous 128B per warp.
    #pragma unroll
    for (int k = 0; k < 16; k++) {
        int idx   = threadIdx.x + k * TPB;     // 0..4095
        int d_loc = idx & 31;
        int s_loc = idx >> 5;                  // 0..127
        g_diag[(size_t)(s0 + s_loc) * DK + d0 + d_loc] = tile[d_loc][s_loc];
    }
}

// Kernel 2: streaming float4 multiply, unroll x8 front-batched loads,
// evict-first on the 268MB x/out streams so the 2MB diag stays L2-resident.
__global__ void __launch_bounds__(TPB) rope_diag_scale_kernel(
    const float4* __restrict__ x4, float4* __restrict__ out4) {
    size_t base = (size_t)blockIdx.x * (TPB * UNROLL) + threadIdx.x;
    const float4* __restrict__ d4 = reinterpret_cast<const float4*>(g_diag);

    float4 xv[UNROLL];
    float4 dv[UNROLL];

    #pragma unroll
    for (int u = 0; u < UNROLL; u++) {
        size_t i = base + (size_t)u * TPB;
        xv[u] = __ldcs(&x4[i]);                       // evict-first stream
    }
    #pragma unroll
    for (int u = 0; u < UNROLL; u++) {
        size_t i = base + (size_t)u * TPB;
        dv[u] = __ldg(&d4[i & (INNER4 - 1)]);         // L2-resident reuse
    }

    #pragma unroll
    for (int u = 0; u < UNROLL; u++) {
        size_t i = base + (size_t)u * TPB;
        float4 ov;
        ov.x = xv[u].x * dv[u].x;
        ov.y = xv[u].y * dv[u].y;
        ov.z = xv[u].z * dv[u].z;
        ov.w = xv[u].w * dv[u].w;
        __stcs(&out4[i], ov);                         // streaming store
    }
}

extern "C" void kernel_launch(void* const* d_in, const int* in_sizes, int n_in,
                              void* d_out, int out_size) {
    const float* x = (const float*)d_in[0];
    // d_in[1] = token_positions (int64) -- unused, as in the reference
    const float* R = (const float*)d_in[2];
    float* out = (float*)d_out;

    diag_gather_kernel<<<(DK / TD) * (SEQ / TS), TPB>>>(R);

    rope_diag_scale_kernel<<<NTOT4 / (TPB * UNROLL), TPB>>>(
        (const float4*)x, (float4*)out);
}

// round 6
// speedup vs baseline: 1.0339x; 1.0057x over previous
#include <cuda_runtime.h>
#include <cstdint>

// x: (8, 16, 4096, 128) fp32, R: (128, 128, 4096) fp32
// out[b,h,s,d] = R[d,d,s] * x[b,h,s,d]
#define SEQ     4096
#define DK      128
#define INNER   (SEQ * DK)          // 524288 elements per (b,h) slice
#define INNER4  (INNER / 4)         // 131072 float4s per slice
#define SLICES  (8 * 16)            // 128 (b,h) slices
#define TPB     256
#define WINDOW_F4   TPB             // 256 float4s per window (8 s x 128 d)
#define NWINDOWS    (INNER4 / WINDOW_F4)   // 512
#define NSLICE_GRP  8
#define SLICES_PB   (SLICES / NSLICE_GRP)  // 16 slices per block
#define UN      8
#define RROW    (129 * 4096)        // element stride between diag rows of R

// Fused kernel: each thread owns one float4 (s,d)-site, fixed across its 16
// slices. Diag values live in 4 registers; x/out stream with evict-first.
__global__ void __launch_bounds__(TPB) rope_fused_kernel(
    const float4* __restrict__ x4, float4* __restrict__ out4,
    const float* __restrict__ R) {

    int win = blockIdx.x & (NWINDOWS - 1);      // 0..511
    int sg  = blockIdx.x >> 9;                  // 0..7
    int w   = win * WINDOW_F4 + threadIdx.x;    // float4 index within a slice
    int d4  = w & 31;                           // float4 index along d
    int s   = w >> 5;                           // 0..4095

    // Diagonal gather: element e = 4w+c -> d = 4*d4+c, diag = R[d*129*4096 + s].
    // Per block this touches only 128 unique 32B sectors (2MB total unique).
    const float* Rp = R + (size_t)(d4 * 4) * RROW + s;
    float dv0 = __ldg(Rp);
    float dv1 = __ldg(Rp + RROW);
    float dv2 = __ldg(Rp + 2 * RROW);
    float dv3 = __ldg(Rp + 3 * RROW);

    size_t base = (size_t)(sg * SLICES_PB) * INNER4 + (size_t)w;

    #pragma unroll 1
    for (int it = 0; it < SLICES_PB / UN; it++) {
        float4 xv[UN];
        // Front-batched loads (MLP=8), 2MB stride between slices,
        // 512B/warp contiguous within a slice.
        #pragma unroll
        for (int u = 0; u < UN; u++)
            xv[u] = __ldcs(&x4[base + (size_t)(it * UN + u) * INNER4]);

        #pragma unroll
        for (int u = 0; u < UN; u++) {
            float4 ov;
            ov.x = xv[u].x * dv0;
            ov.y = xv[u].y * dv1;
            ov.z = xv[u].z * dv2;
            ov.w = xv[u].w * dv3;
            __stcs(&out4[base + (size_t)(it * UN + u) * INNER4], ov);
        }
    }
}

extern "C" void kernel_launch(void* const* d_in, const int* in_sizes, int n_in,
                              void* d_out, int out_size) {
    const float* x = (const float*)d_in[0];
    // d_in[1] = token_positions (int64) -- unused, as in the reference
    const float* R = (const float*)d_in[2];
    float* out = (float*)d_out;

    rope_fused_kernel<<<NWINDOWS * NSLICE_GRP, TPB>>>(
        (const float4*)x, (float4*)out, R);
}